// round 8
// baseline (speedup 1.0000x reference)
#include <cuda_runtime.h>
#include <cuda_bf16.h>
#include <math.h>
#include <stdint.h>

// Problem dims (fixed by the dataset)
#define Bsz  8192
#define DIN  1024
#define HH   2048
#define DOUT 1000
#define MT   (Bsz / 128)     // 64 m-tiles -> BN partial chunks

// ---------------- scratch (device globals) ----------------------------------
__device__ __align__(256) float  g_act[Bsz * HH];
__device__ __align__(256) float  g_logits[Bsz * DOUT];
__device__ __align__(256) __nv_bfloat16 g_A1[(size_t)Bsz * 2 * DIN];   // [hi|lo]
__device__ __align__(256) __nv_bfloat16 g_A2[(size_t)Bsz * 2 * HH];    // [hi|lo]
__device__ __align__(256) __nv_bfloat16 g_W1[(size_t)HH * 2 * DIN];
__device__ __align__(256) __nv_bfloat16 g_W2[(size_t)HH * 2 * HH];
__device__ __align__(256) __nv_bfloat16 g_W3[(size_t)1024 * 2 * HH];   // rows 1000.. zero
__device__ float g_psumf[MT * HH];
__device__ float g_psqf [MT * HH];
__device__ float g_mu[HH], g_rstd[HH];

// ---------------- helpers -----------------------------------------------------
__device__ __forceinline__ uint32_t smem_to_u32(const void* p) {
    uint32_t a;
    asm("{ .reg .u64 t; cvta.to.shared.u64 t, %1; cvt.u32.u64 %0, t; }" : "=r"(a) : "l"(p));
    return a;
}
#define SW128(off) ((off) ^ (((off) >> 3) & 0x70))

__device__ __forceinline__ void cp_async16(uint32_t daddr, const void* gptr) {
    asm volatile("cp.async.cg.shared.global [%0], [%1], 16;" :: "r"(daddr), "l"(gptr));
}
__device__ __forceinline__ void cp_commit() { asm volatile("cp.async.commit_group;"); }
template <int N>
__device__ __forceinline__ void cp_wait() { asm volatile("cp.async.wait_group %0;" :: "n"(N)); }

__device__ __forceinline__ void ldm_x4(uint32_t* r, uint32_t addr) {
    asm volatile("ldmatrix.sync.aligned.m8n8.x4.shared.b16 {%0,%1,%2,%3}, [%4];"
                 : "=r"(r[0]), "=r"(r[1]), "=r"(r[2]), "=r"(r[3]) : "r"(addr));
}
__device__ __forceinline__ void mma16816(float* d, const uint32_t* a, const uint32_t* b) {
    asm volatile(
        "mma.sync.aligned.m16n8k16.row.col.f32.bf16.bf16.f32 "
        "{%0,%1,%2,%3}, {%4,%5,%6,%7}, {%8,%9}, {%0,%1,%2,%3};"
        : "+f"(d[0]), "+f"(d[1]), "+f"(d[2]), "+f"(d[3])
        : "r"(a[0]), "r"(a[1]), "r"(a[2]), "r"(a[3]), "r"(b[0]), "r"(b[1]));
}

// ---------------- bf16x3-split HMMA GEMM, CTA tile 128x256 -------------------
// Virtual K = 3*Kreal, segments: 0:(Ah,Bh) 1:(Ah,Bl) 2:(Al,Bh).
// BK=64 bf16. 8 warps = 2(M) x 4(N), warp tile 64x64. 3-stage cp.async,
// 1 CTA/SM (144 KB smem). Epilogue optionally emits per-column BN partials.
static constexpr int TILE_A   = 128 * 128;                 // 16 KB
static constexpr int TILE_B   = 256 * 128;                 // 32 KB
static constexpr int STAGE_SZ = TILE_A + TILE_B;           // 48 KB
static constexpr int SMEM_TOT = 3 * STAGE_SZ + 1024;

template <int KSHIFT, bool STATS>
__global__ void __launch_bounds__(256, 1)
gemm_mma(const __nv_bfloat16* __restrict__ Ahi, const __nv_bfloat16* __restrict__ Alo,
         const __nv_bfloat16* __restrict__ Bhi, const __nv_bfloat16* __restrict__ Blo,
         const float* __restrict__ bias, float* __restrict__ C,
         int Nreal, int Kreal, float* __restrict__ psum, float* __restrict__ psq) {
    extern __shared__ uint8_t smem_raw[];
    uint32_t sb = smem_to_u32(smem_raw);
    sb = (sb + 1023) & ~1023u;

    const int tid  = threadIdx.x;
    const int wid  = tid >> 5, lane = tid & 31;
    const int m0   = blockIdx.y * 128, n0 = blockIdx.x * 256;
    const int wM   = wid >> 2;          // 0..1 -> 64-row slab
    const int wN   = wid & 3;           // 0..3 -> 64-col slab
    constexpr int NC    = 3 << KSHIFT;
    constexpr int CMASK = (1 << KSHIFT) - 1;

    auto prefetch = [&](int c, int st) {
        const int seg = c >> KSHIFT;
        const int k0  = (c & CMASK) * 64;
        const __nv_bfloat16* As = (seg == 2) ? Alo : Ahi;
        const __nv_bfloat16* Bs = (seg == 1) ? Blo : Bhi;
        const uint32_t baseA = sb + (uint32_t)st * STAGE_SZ;
        const uint32_t baseB = baseA + TILE_A;
#pragma unroll
        for (int i = 0; i < 4; i++) {                    // A: 128 rows
            int slot = tid + i * 256;
            int row = slot >> 3, s16 = slot & 7;
            uint32_t so = SW128((uint32_t)(row * 128 + s16 * 16));
            cp_async16(baseA + so, As + (size_t)(m0 + row) * Kreal + k0 + s16 * 8);
        }
#pragma unroll
        for (int i = 0; i < 8; i++) {                    // B: 256 rows
            int slot = tid + i * 256;
            int row = slot >> 3, s16 = slot & 7;
            uint32_t so = SW128((uint32_t)(row * 128 + s16 * 16));
            cp_async16(baseB + so, Bs + (size_t)(n0 + row) * Kreal + k0 + s16 * 8);
        }
        cp_commit();
    };

    float acc[4][8][4];
#pragma unroll
    for (int i = 0; i < 4; i++)
#pragma unroll
        for (int j = 0; j < 8; j++)
#pragma unroll
            for (int q = 0; q < 4; q++) acc[i][j][q] = 0.f;

    const int aRow = wM * 64 + (lane & 15);
    const int aCol = ((lane >> 4) & 1) * 16;
    const int bRow = wN * 64 + (lane & 7) + ((lane >> 4) & 1) * 8;
    const int bCol = ((lane >> 3) & 1) * 16;

    prefetch(0, 0);
    prefetch(1, 1);

    int st = 0;
    for (int c = 0; c < NC; c++) {
        if (c + 1 < NC) cp_wait<1>(); else cp_wait<0>();
        __syncthreads();
        if (c + 2 < NC) {
            int st2 = st + 2; if (st2 >= 3) st2 -= 3;
            prefetch(c + 2, st2);
        }

        const uint32_t bufA = sb + (uint32_t)st * STAGE_SZ;
        const uint32_t bufB = bufA + TILE_A;
#pragma unroll
        for (int s = 0; s < 4; s++) {
            uint32_t afr[4][4];
#pragma unroll
            for (int mi = 0; mi < 4; mi++) {
                uint32_t addr = bufA + SW128((uint32_t)((aRow + mi * 16) * 128 + s * 32 + aCol));
                ldm_x4(afr[mi], addr);
            }
            uint32_t bfr[8][2];
#pragma unroll
            for (int nh = 0; nh < 4; nh++) {
                uint32_t r[4];
                uint32_t addr = bufB + SW128((uint32_t)((bRow + nh * 16) * 128 + s * 32 + bCol));
                ldm_x4(r, addr);
                bfr[nh * 2][0] = r[0]; bfr[nh * 2][1] = r[1];
                bfr[nh * 2 + 1][0] = r[2]; bfr[nh * 2 + 1][1] = r[3];
            }
#pragma unroll
            for (int mi = 0; mi < 4; mi++)
#pragma unroll
                for (int ni = 0; ni < 8; ni++)
                    mma16816(acc[mi][ni], afr[mi], bfr[ni]);
        }
        if (++st == 3) st = 0;
    }

    // epilogue: bias + store + optional per-column stats partials
    float s16v[16], q16v[16];
    if (STATS) {
#pragma unroll
        for (int i = 0; i < 16; i++) { s16v[i] = 0.f; q16v[i] = 0.f; }
    }
#pragma unroll
    for (int mi = 0; mi < 4; mi++) {
        const int row = m0 + wM * 64 + mi * 16 + (lane >> 2);
#pragma unroll
        for (int ni = 0; ni < 8; ni++) {
            const int col = n0 + wN * 64 + ni * 8 + (lane & 3) * 2;
            if (col < Nreal) {
                const float b0 = bias[col], b1 = bias[col + 1];
                float v00 = acc[mi][ni][0] + b0, v01 = acc[mi][ni][1] + b1;
                float v10 = acc[mi][ni][2] + b0, v11 = acc[mi][ni][3] + b1;
                *reinterpret_cast<float2*>(&C[(size_t)row * Nreal + col]) = make_float2(v00, v01);
                *reinterpret_cast<float2*>(&C[(size_t)(row + 8) * Nreal + col]) = make_float2(v10, v11);
                if (STATS) {
                    s16v[ni * 2]     += v00 + v10;
                    s16v[ni * 2 + 1] += v01 + v11;
                    q16v[ni * 2]     += v00 * v00 + v10 * v10;
                    q16v[ni * 2 + 1] += v01 * v01 + v11 * v11;
                }
            }
        }
    }

    if (STATS) {
        // reduce over the 8 lanes sharing a column (lane>>2 varies, lane&3 fixed)
#pragma unroll
        for (int o = 16; o >= 4; o >>= 1)
#pragma unroll
            for (int i = 0; i < 16; i++) {
                s16v[i] += __shfl_xor_sync(0xffffffffu, s16v[i], o);
                q16v[i] += __shfl_xor_sync(0xffffffffu, q16v[i], o);
            }
        __syncthreads();                  // stage buffers now safe to reuse
        float* sred = reinterpret_cast<float*>(smem_raw);      // [2][256]
        float* qred = sred + 512;                              // [2][256]
        if (lane < 4) {
#pragma unroll
            for (int i = 0; i < 16; i++) {
                int colT = wN * 64 + (i >> 1) * 8 + lane * 2 + (i & 1);
                sred[wM * 256 + colT] = s16v[i];
                qred[wM * 256 + colT] = q16v[i];
            }
        }
        __syncthreads();
        {
            const int mt = blockIdx.y;
            psum[(size_t)mt * Nreal + n0 + tid] = sred[tid] + sred[256 + tid];
            psq [(size_t)mt * Nreal + n0 + tid] = qred[tid] + qred[256 + tid];
        }
    }
}

// ---------------- bf16 hi/lo split conversion ([hi | lo] halves) -------------
__global__ __launch_bounds__(256)
void convert_split(const float* __restrict__ X, __nv_bfloat16* __restrict__ Y,
                   int R, int K, int Mtot) {
    const int r = blockIdx.x;
    __nv_bfloat16* Yh = Y + (size_t)r * K;
    __nv_bfloat16* Yl = Y + (size_t)Mtot * K + (size_t)r * K;
    if (r >= R) {
        __nv_bfloat162 z; z.x = __float2bfloat16(0.f); z.y = z.x;
        for (int j = threadIdx.x * 2; j < K; j += 512) {
            *reinterpret_cast<__nv_bfloat162*>(&Yh[j]) = z;
            *reinterpret_cast<__nv_bfloat162*>(&Yl[j]) = z;
        }
        return;
    }
    for (int j = threadIdx.x * 2; j < K; j += 512) {
        float v0 = X[(size_t)r * K + j], v1 = X[(size_t)r * K + j + 1];
        __nv_bfloat162 hp, lp;
        hp.x = __float2bfloat16(v0); hp.y = __float2bfloat16(v1);
        lp.x = __float2bfloat16(v0 - __bfloat162float(hp.x));
        lp.y = __float2bfloat16(v1 - __bfloat162float(hp.y));
        *reinterpret_cast<__nv_bfloat162*>(&Yh[j]) = hp;
        *reinterpret_cast<__nv_bfloat162*>(&Yl[j]) = lp;
    }
}

// ---------------- BN finalize (64 fp32 partials -> mu/rstd, double) ----------
__global__ void bn_finalize() {
    int j = blockIdx.x * blockDim.x + threadIdx.x;
    if (j >= HH) return;
    double s = 0.0, ss = 0.0;
    for (int c = 0; c < MT; c++) {
        s  += (double)g_psumf[(size_t)c * HH + j];
        ss += (double)g_psqf [(size_t)c * HH + j];
    }
    double mu  = s / (double)Bsz;
    double var = ss / (double)Bsz - mu * mu;
    g_mu[j]   = (float)mu;
    g_rstd[j] = (float)(1.0 / sqrt(var + 1e-5));
}

// ---------------- block reductions -------------------------------------------
__device__ __forceinline__ float block_sum256(float v) {
#pragma unroll
    for (int o = 16; o > 0; o >>= 1) v += __shfl_down_sync(0xffffffffu, v, o);
    __shared__ float sh[9];
    int w = threadIdx.x >> 5, l = threadIdx.x & 31;
    if (l == 0) sh[w] = v;
    __syncthreads();
    if (threadIdx.x == 0) {
        float t = 0.f;
#pragma unroll
        for (int q = 0; q < 8; q++) t += sh[q];
        sh[8] = t;
    }
    __syncthreads();
    return sh[8];
}
__device__ __forceinline__ float block_max256(float v) {
#pragma unroll
    for (int o = 16; o > 0; o >>= 1) v = fmaxf(v, __shfl_down_sync(0xffffffffu, v, o));
    __shared__ float sh[9];
    int w = threadIdx.x >> 5, l = threadIdx.x & 31;
    if (l == 0) sh[w] = v;
    __syncthreads();
    if (threadIdx.x == 0) {
        float t = sh[0];
#pragma unroll
        for (int q = 1; q < 8; q++) t = fmaxf(t, sh[q]);
        sh[8] = t;
    }
    __syncthreads();
    return sh[8];
}

// ---------------- stage 1: BN+relu+e2p+log0 -> bf16 [hi|lo] ------------------
__global__ __launch_bounds__(256)
void rowmap_stage1(const float* __restrict__ act, const float* __restrict__ gm,
                   const float* __restrict__ bt, __nv_bfloat16* __restrict__ out) {
    const int row = blockIdx.x;
    float h[8];
    float ssq = 0.f;
#pragma unroll
    for (int p = 0; p < 4; p++) {
        int j = p * 512 + threadIdx.x * 2;
        float y0 = act[(size_t)row * HH + j];
        float y1 = act[(size_t)row * HH + j + 1];
        float v0 = fmaxf(gm[j] * (y0 - g_mu[j]) * g_rstd[j] + bt[j], 0.f);
        float v1 = fmaxf(gm[j + 1] * (y1 - g_mu[j + 1]) * g_rstd[j + 1] + bt[j + 1], 0.f);
        h[2 * p] = v0; h[2 * p + 1] = v1;
        ssq += v0 * v0 + v1 * v1;
    }
    float tot = block_sum256(ssq);
    float n = sqrtf(tot);
    float coef = 0.f;
    if (n > 0.f) {
        const float sc = 0.31622776601683794f;
        float th = tanhf(sc * n);
        float s  = 0.9f * th / (sc * n);
        float ny = 0.9f * th / sc;
        float dn = fmaxf(ny, 1e-8f);
        coef = -s * atanhf(sc * dn) / (sc * dn);
    }
    __nv_bfloat16* Yh = out + (size_t)row * HH;
    __nv_bfloat16* Yl = out + (size_t)Bsz * HH + (size_t)row * HH;
#pragma unroll
    for (int p = 0; p < 4; p++) {
        int j = p * 512 + threadIdx.x * 2;
        float v0 = coef * h[2 * p], v1 = coef * h[2 * p + 1];
        __nv_bfloat162 hp, lp;
        hp.x = __float2bfloat16(v0); hp.y = __float2bfloat16(v1);
        lp.x = __float2bfloat16(v0 - __bfloat162float(hp.x));
        lp.y = __float2bfloat16(v1 - __bfloat162float(hp.y));
        *reinterpret_cast<__nv_bfloat162*>(&Yh[j]) = hp;
        *reinterpret_cast<__nv_bfloat162*>(&Yl[j]) = lp;
    }
}

// ---------------- stage 2: BN+relu+exp0+p2e -> bf16 [hi|lo] ------------------
__global__ __launch_bounds__(256)
void rowmap_stage2(const float* __restrict__ act, const float* __restrict__ gm,
                   const float* __restrict__ bt, __nv_bfloat16* __restrict__ out) {
    const int row = blockIdx.x;
    float h[8];
    float ssq = 0.f;
#pragma unroll
    for (int p = 0; p < 4; p++) {
        int j = p * 512 + threadIdx.x * 2;
        float y0 = act[(size_t)row * HH + j];
        float y1 = act[(size_t)row * HH + j + 1];
        float v0 = fmaxf(gm[j] * (y0 - g_mu[j]) * g_rstd[j] + bt[j], 0.f);
        float v1 = fmaxf(gm[j + 1] * (y1 - g_mu[j + 1]) * g_rstd[j + 1] + bt[j + 1], 0.f);
        h[2 * p] = v0; h[2 * p + 1] = v1;
        ssq += v0 * v0 + v1 * v1;
    }
    float tot = block_sum256(ssq);
    float n = sqrtf(tot);
    const float sc = 0.31622776601683794f;
    float vn  = fmaxf(n, 1e-8f);
    float scl = tanhf(sc * vn) / (sc * vn);
    float nn  = scl * n;
    float nnc = fminf(fmaxf(nn, 1e-8f), 1.0f);
    float coef = scl * atanhf(sc * nnc) / (sc * nnc);
    __nv_bfloat16* Yh = out + (size_t)row * HH;
    __nv_bfloat16* Yl = out + (size_t)Bsz * HH + (size_t)row * HH;
#pragma unroll
    for (int p = 0; p < 4; p++) {
        int j = p * 512 + threadIdx.x * 2;
        float v0 = coef * h[2 * p], v1 = coef * h[2 * p + 1];
        __nv_bfloat162 hp, lp;
        hp.x = __float2bfloat16(v0); hp.y = __float2bfloat16(v1);
        lp.x = __float2bfloat16(v0 - __bfloat162float(hp.x));
        lp.y = __float2bfloat16(v1 - __bfloat162float(hp.y));
        *reinterpret_cast<__nv_bfloat162*>(&Yh[j]) = hp;
        *reinterpret_cast<__nv_bfloat162*>(&Yl[j]) = lp;
    }
}

// ---------------- log_softmax over 1000 cols ---------------------------------
__global__ __launch_bounds__(256)
void log_softmax_kernel(const float* __restrict__ logits, float* __restrict__ out) {
    const int row = blockIdx.x;
    float x[4];
    float mx = -1e30f;
#pragma unroll
    for (int k = 0; k < 4; k++) {
        int j = k * 256 + threadIdx.x;
        x[k] = (j < DOUT) ? logits[(size_t)row * DOUT + j] : -1e30f;
        mx = fmaxf(mx, x[k]);
    }
    mx = block_max256(mx);
    float se = 0.f;
#pragma unroll
    for (int k = 0; k < 4; k++) {
        int j = k * 256 + threadIdx.x;
        if (j < DOUT) se += expf(x[k] - mx);
    }
    se = block_sum256(se);
    float lse = logf(se);
#pragma unroll
    for (int k = 0; k < 4; k++) {
        int j = k * 256 + threadIdx.x;
        if (j < DOUT) out[(size_t)row * DOUT + j] = x[k] - mx - lse;
    }
}

// ---------------- launcher ----------------------------------------------------
extern "C" void kernel_launch(void* const* d_in, const int* in_sizes, int n_in,
                              void* d_out, int out_size) {
    const float* x   = (const float*)d_in[0];
    const float* W1  = (const float*)d_in[1];
    const float* b1  = (const float*)d_in[2];
    const float* g1  = (const float*)d_in[3];
    const float* be1 = (const float*)d_in[4];
    const float* W2  = (const float*)d_in[5];
    const float* b2  = (const float*)d_in[6];
    const float* g2  = (const float*)d_in[7];
    const float* be2 = (const float*)d_in[8];
    const float* W3  = (const float*)d_in[9];
    const float* b3  = (const float*)d_in[10];
    float* out = (float*)d_out;

    float *act, *logits, *psum, *psq;
    __nv_bfloat16 *A1, *A2, *Wb1, *Wb2, *Wb3;
    cudaGetSymbolAddress((void**)&act,    g_act);
    cudaGetSymbolAddress((void**)&logits, g_logits);
    cudaGetSymbolAddress((void**)&psum,   g_psumf);
    cudaGetSymbolAddress((void**)&psq,    g_psqf);
    cudaGetSymbolAddress((void**)&A1,     g_A1);
    cudaGetSymbolAddress((void**)&A2,     g_A2);
    cudaGetSymbolAddress((void**)&Wb1,    g_W1);
    cudaGetSymbolAddress((void**)&Wb2,    g_W2);
    cudaGetSymbolAddress((void**)&Wb3,    g_W3);

    cudaFuncSetAttribute(gemm_mma<4, true>,  cudaFuncAttributeMaxDynamicSharedMemorySize, SMEM_TOT);
    cudaFuncSetAttribute(gemm_mma<5, true>,  cudaFuncAttributeMaxDynamicSharedMemorySize, SMEM_TOT);
    cudaFuncSetAttribute(gemm_mma<5, false>, cudaFuncAttributeMaxDynamicSharedMemorySize, SMEM_TOT);

    dim3 blk(256);

    // converts (gemm L1 placed at launch index 3 so the profiler lands on it)
    convert_split<<<HH, blk>>>(W1, Wb1, HH, DIN, HH);
    convert_split<<<Bsz, blk>>>(x, A1, Bsz, DIN, Bsz);
    convert_split<<<HH, blk>>>(W2, Wb2, HH, HH, HH);

    // Layer 1: grid (2048/256, 8192/128) = (8, 64)
    gemm_mma<4, true><<<dim3(HH / 256, Bsz / 128), blk, SMEM_TOT>>>(
        A1, A1 + (size_t)Bsz * DIN, Wb1, Wb1 + (size_t)HH * DIN, b1, act, HH, DIN, psum, psq);
    bn_finalize<<<8, 256>>>();
    rowmap_stage1<<<Bsz, blk>>>(act, g1, be1, A2);
    convert_split<<<1024, blk>>>(W3, Wb3, DOUT, HH, 1024);

    // Layer 2: grid (8, 64)
    gemm_mma<5, true><<<dim3(HH / 256, Bsz / 128), blk, SMEM_TOT>>>(
        A2, A2 + (size_t)Bsz * HH, Wb2, Wb2 + (size_t)HH * HH, b2, act, HH, HH, psum, psq);
    bn_finalize<<<8, 256>>>();
    rowmap_stage2<<<Bsz, blk>>>(act, g2, be2, A2);

    // Layer 3: grid (1024/256, 64) = (4, 64)
    gemm_mma<5, false><<<dim3(1024 / 256, Bsz / 128), blk, SMEM_TOT>>>(
        A2, A2 + (size_t)Bsz * HH, Wb3, Wb3 + (size_t)1024 * HH, b3, logits, DOUT, HH, nullptr, nullptr);
    log_softmax_kernel<<<Bsz, blk>>>(logits, out);
}

// round 9
// speedup vs baseline: 1.5861x; 1.5861x over previous
#include <cuda_runtime.h>
#include <cuda_fp16.h>
#include <math.h>
#include <stdint.h>

// Problem dims (fixed by the dataset)
#define Bsz  8192
#define DIN  1024
#define HH   2048
#define DOUT 1000
#define MT   (Bsz / 128)     // 64 m-tiles -> BN partial chunks

// ---------------- scratch (device globals) ----------------------------------
__device__ __align__(256) float  g_act[Bsz * HH];
__device__ __align__(256) float  g_logits[Bsz * DOUT];
__device__ __align__(256) __half g_A1[(size_t)Bsz * 2 * DIN];   // [hi|lo]
__device__ __align__(256) __half g_A2[(size_t)Bsz * 2 * HH];    // [hi|lo]
__device__ __align__(256) __half g_W1[(size_t)HH * DIN];        // fp16 hi only
__device__ __align__(256) __half g_W2[(size_t)HH * HH];
__device__ __align__(256) __half g_W3[(size_t)1024 * HH];       // rows 1000.. zero
__device__ float g_psumf[MT * HH];
__device__ float g_psqf [MT * HH];
__device__ float g_mu[HH], g_rstd[HH];

// ---------------- helpers -----------------------------------------------------
__device__ __forceinline__ uint32_t smem_to_u32(const void* p) {
    uint32_t a;
    asm("{ .reg .u64 t; cvta.to.shared.u64 t, %1; cvt.u32.u64 %0, t; }" : "=r"(a) : "l"(p));
    return a;
}
#define SW128(off) ((off) ^ (((off) >> 3) & 0x70))

__device__ __forceinline__ void cp_async16(uint32_t daddr, const void* gptr) {
    asm volatile("cp.async.cg.shared.global [%0], [%1], 16;" :: "r"(daddr), "l"(gptr));
}
__device__ __forceinline__ void cp_commit() { asm volatile("cp.async.commit_group;"); }
template <int N>
__device__ __forceinline__ void cp_wait() { asm volatile("cp.async.wait_group %0;" :: "n"(N)); }

__device__ __forceinline__ void ldm_x4(uint32_t* r, uint32_t addr) {
    asm volatile("ldmatrix.sync.aligned.m8n8.x4.shared.b16 {%0,%1,%2,%3}, [%4];"
                 : "=r"(r[0]), "=r"(r[1]), "=r"(r[2]), "=r"(r[3]) : "r"(addr));
}
__device__ __forceinline__ void mma16816(float* d, const uint32_t* a, const uint32_t* b) {
    asm volatile(
        "mma.sync.aligned.m16n8k16.row.col.f32.f16.f16.f32 "
        "{%0,%1,%2,%3}, {%4,%5,%6,%7}, {%8,%9}, {%0,%1,%2,%3};"
        : "+f"(d[0]), "+f"(d[1]), "+f"(d[2]), "+f"(d[3])
        : "r"(a[0]), "r"(a[1]), "r"(a[2]), "r"(a[3]), "r"(b[0]), "r"(b[1]));
}

// ---------------- fp16 2-pass split HMMA GEMM (R7 config) --------------------
// Virtual K = 2*Kreal, segments: 0:(Ah,Bh) 1:(Al,Bh). B is fp16 hi only.
// CTA tile 128x128, BK=64 fp16. 8 warps = 2(M) x 4(N), warp tile 64x32.
// 3-stage cp.async pipeline, 2 CTAs/SM. Epilogue optionally emits per-column
// BN sum/sumsq partials (deterministic, no atomics).
static constexpr int TILE_BYTES = 128 * 128;              // 16 KB (A or B, one stage)
static constexpr int SMEM_TOT   = 6 * TILE_BYTES + 1024;  // 3 stages x (A+B)

template <int KSHIFT, bool STATS>
__global__ void __launch_bounds__(256, 2)
gemm_mma(const __half* __restrict__ Ahi, const __half* __restrict__ Alo,
         const __half* __restrict__ Bh,
         const float* __restrict__ bias, float* __restrict__ C,
         int Nreal, int Kreal, float* __restrict__ psum, float* __restrict__ psq) {
    extern __shared__ uint8_t smem_raw[];
    uint32_t sb = smem_to_u32(smem_raw);
    sb = (sb + 1023) & ~1023u;

    const int tid  = threadIdx.x;
    const int wid  = tid >> 5, lane = tid & 31;
    const int m0   = blockIdx.y * 128, n0 = blockIdx.x * 128;
    const int wM   = wid >> 2;          // 0..1 -> 64-row slab
    const int wN   = wid & 3;           // 0..3 -> 32-col slab
    constexpr int NC    = 2 << KSHIFT;
    constexpr int CMASK = (1 << KSHIFT) - 1;

    auto prefetch = [&](int c, int st) {
        const int seg = c >> KSHIFT;
        const int k0  = (c & CMASK) * 64;
        const __half* As = seg ? Alo : Ahi;
        const uint32_t baseA = sb + (uint32_t)st * 2 * TILE_BYTES;
        const uint32_t baseB = baseA + TILE_BYTES;
#pragma unroll
        for (int i = 0; i < 4; i++) {
            int slot = tid + i * 256;
            int row = slot >> 3, s16 = slot & 7;
            uint32_t so = SW128((uint32_t)(row * 128 + s16 * 16));
            cp_async16(baseA + so, As + (size_t)(m0 + row) * Kreal + k0 + s16 * 8);
            cp_async16(baseB + so, Bh + (size_t)(n0 + row) * Kreal + k0 + s16 * 8);
        }
        cp_commit();
    };

    float acc[4][4][4];
#pragma unroll
    for (int i = 0; i < 4; i++)
#pragma unroll
        for (int j = 0; j < 4; j++)
#pragma unroll
            for (int q = 0; q < 4; q++) acc[i][j][q] = 0.f;

    const int aRow = wM * 64 + (lane & 15);
    const int aCol = ((lane >> 4) & 1) * 16;
    const int bRow = wN * 32 + (lane & 7) + ((lane >> 4) & 1) * 8;
    const int bCol = ((lane >> 3) & 1) * 16;

    prefetch(0, 0);
    prefetch(1, 1);

    int st = 0;
    for (int c = 0; c < NC; c++) {
        if (c + 1 < NC) cp_wait<1>(); else cp_wait<0>();
        __syncthreads();
        if (c + 2 < NC) {
            int st2 = st + 2; if (st2 >= 3) st2 -= 3;
            prefetch(c + 2, st2);
        }

        const uint32_t bufA = sb + (uint32_t)st * 2 * TILE_BYTES;
        const uint32_t bufB = bufA + TILE_BYTES;
#pragma unroll
        for (int s = 0; s < 4; s++) {
            uint32_t afr[4][4];
#pragma unroll
            for (int mi = 0; mi < 4; mi++) {
                uint32_t addr = bufA + SW128((uint32_t)((aRow + mi * 16) * 128 + s * 32 + aCol));
                ldm_x4(afr[mi], addr);
            }
            uint32_t bfr[4][2];
#pragma unroll
            for (int nh = 0; nh < 2; nh++) {
                uint32_t r[4];
                uint32_t addr = bufB + SW128((uint32_t)((bRow + nh * 16) * 128 + s * 32 + bCol));
                ldm_x4(r, addr);
                bfr[nh * 2][0] = r[0]; bfr[nh * 2][1] = r[1];
                bfr[nh * 2 + 1][0] = r[2]; bfr[nh * 2 + 1][1] = r[3];
            }
#pragma unroll
            for (int mi = 0; mi < 4; mi++)
#pragma unroll
                for (int ni = 0; ni < 4; ni++)
                    mma16816(acc[mi][ni], afr[mi], bfr[ni]);
        }
        if (++st == 3) st = 0;
    }

    // epilogue: bias + store + optional per-column stats partials
    float s8[8], q8[8];
    if (STATS) {
#pragma unroll
        for (int i = 0; i < 8; i++) { s8[i] = 0.f; q8[i] = 0.f; }
    }
#pragma unroll
    for (int mi = 0; mi < 4; mi++) {
        const int row = m0 + wM * 64 + mi * 16 + (lane >> 2);
#pragma unroll
        for (int ni = 0; ni < 4; ni++) {
            const int col = n0 + wN * 32 + ni * 8 + (lane & 3) * 2;
            if (col < Nreal) {
                const float b0 = bias[col], b1 = bias[col + 1];
                float v00 = acc[mi][ni][0] + b0, v01 = acc[mi][ni][1] + b1;
                float v10 = acc[mi][ni][2] + b0, v11 = acc[mi][ni][3] + b1;
                *reinterpret_cast<float2*>(&C[(size_t)row * Nreal + col]) = make_float2(v00, v01);
                *reinterpret_cast<float2*>(&C[(size_t)(row + 8) * Nreal + col]) = make_float2(v10, v11);
                if (STATS) {
                    s8[ni * 2]     += v00 + v10;
                    s8[ni * 2 + 1] += v01 + v11;
                    q8[ni * 2]     += v00 * v00 + v10 * v10;
                    q8[ni * 2 + 1] += v01 * v01 + v11 * v11;
                }
            }
        }
    }

    if (STATS) {
        // reduce over the 8 lanes sharing a column (lane>>2 varies, lane&3 fixed)
#pragma unroll
        for (int o = 16; o >= 4; o >>= 1)
#pragma unroll
            for (int i = 0; i < 8; i++) {
                s8[i] += __shfl_xor_sync(0xffffffffu, s8[i], o);
                q8[i] += __shfl_xor_sync(0xffffffffu, q8[i], o);
            }
        __syncthreads();                  // stage buffers now safe to reuse
        float* sred = reinterpret_cast<float*>(smem_raw);      // [2][128]
        float* qred = sred + 256;                              // [2][128]
        if (lane < 4) {
#pragma unroll
            for (int i = 0; i < 8; i++) {
                int colT = wN * 32 + (i >> 1) * 8 + lane * 2 + (i & 1);
                sred[wM * 128 + colT] = s8[i];
                qred[wM * 128 + colT] = q8[i];
            }
        }
        __syncthreads();
        if (tid < 128) {
            const int mt = blockIdx.y;
            psum[(size_t)mt * Nreal + n0 + tid] = sred[tid] + sred[128 + tid];
            psq [(size_t)mt * Nreal + n0 + tid] = qred[tid] + qred[128 + tid];
        }
    }
}

// ---------------- fp16 hi/lo split conversion (activations) ------------------
__global__ __launch_bounds__(256)
void convert_split(const float* __restrict__ X, __half* __restrict__ Y,
                   int K, int Mtot) {
    const int r = blockIdx.x;
    __half* Yh = Y + (size_t)r * K;
    __half* Yl = Y + (size_t)Mtot * K + (size_t)r * K;
    for (int j = threadIdx.x * 2; j < K; j += 512) {
        float v0 = X[(size_t)r * K + j], v1 = X[(size_t)r * K + j + 1];
        __half2 hp, lp;
        hp.x = __float2half_rn(v0); hp.y = __float2half_rn(v1);
        lp.x = __float2half_rn(v0 - __half2float(hp.x));
        lp.y = __float2half_rn(v1 - __half2float(hp.y));
        *reinterpret_cast<__half2*>(&Yh[j]) = hp;
        *reinterpret_cast<__half2*>(&Yl[j]) = lp;
    }
}

// ---------------- fp16 single conversion (weights, zero-pad rows) ------------
__global__ __launch_bounds__(256)
void convert_h(const float* __restrict__ X, __half* __restrict__ Y, int R, int K) {
    const int r = blockIdx.x;
    __half* Yr = Y + (size_t)r * K;
    if (r >= R) {
        __half2 z; z.x = __float2half(0.f); z.y = z.x;
        for (int j = threadIdx.x * 2; j < K; j += 512)
            *reinterpret_cast<__half2*>(&Yr[j]) = z;
        return;
    }
    for (int j = threadIdx.x * 2; j < K; j += 512) {
        __half2 hp;
        hp.x = __float2half_rn(X[(size_t)r * K + j]);
        hp.y = __float2half_rn(X[(size_t)r * K + j + 1]);
        *reinterpret_cast<__half2*>(&Yr[j]) = hp;
    }
}

// ---------------- BN finalize (64 fp32 partials -> mu/rstd, double) ----------
__global__ void bn_finalize() {
    int j = blockIdx.x * blockDim.x + threadIdx.x;
    if (j >= HH) return;
    double s = 0.0, ss = 0.0;
    for (int c = 0; c < MT; c++) {
        s  += (double)g_psumf[(size_t)c * HH + j];
        ss += (double)g_psqf [(size_t)c * HH + j];
    }
    double mu  = s / (double)Bsz;
    double var = ss / (double)Bsz - mu * mu;
    g_mu[j]   = (float)mu;
    g_rstd[j] = (float)(1.0 / sqrt(var + 1e-5));
}

// ---------------- block reductions -------------------------------------------
__device__ __forceinline__ float block_sum256(float v) {
#pragma unroll
    for (int o = 16; o > 0; o >>= 1) v += __shfl_down_sync(0xffffffffu, v, o);
    __shared__ float sh[9];
    int w = threadIdx.x >> 5, l = threadIdx.x & 31;
    if (l == 0) sh[w] = v;
    __syncthreads();
    if (threadIdx.x == 0) {
        float t = 0.f;
#pragma unroll
        for (int q = 0; q < 8; q++) t += sh[q];
        sh[8] = t;
    }
    __syncthreads();
    return sh[8];
}
__device__ __forceinline__ float block_max256(float v) {
#pragma unroll
    for (int o = 16; o > 0; o >>= 1) v = fmaxf(v, __shfl_down_sync(0xffffffffu, v, o));
    __shared__ float sh[9];
    int w = threadIdx.x >> 5, l = threadIdx.x & 31;
    if (l == 0) sh[w] = v;
    __syncthreads();
    if (threadIdx.x == 0) {
        float t = sh[0];
#pragma unroll
        for (int q = 1; q < 8; q++) t = fmaxf(t, sh[q]);
        sh[8] = t;
    }
    __syncthreads();
    return sh[8];
}

// ---------------- stage 1: BN+relu+e2p+log0 -> fp16 [hi|lo] ------------------
__global__ __launch_bounds__(256)
void rowmap_stage1(const float* __restrict__ act, const float* __restrict__ gm,
                   const float* __restrict__ bt, __half* __restrict__ out) {
    const int row = blockIdx.x;
    float h[8];
    float ssq = 0.f;
#pragma unroll
    for (int p = 0; p < 4; p++) {
        int j = p * 512 + threadIdx.x * 2;
        float y0 = act[(size_t)row * HH + j];
        float y1 = act[(size_t)row * HH + j + 1];
        float v0 = fmaxf(gm[j] * (y0 - g_mu[j]) * g_rstd[j] + bt[j], 0.f);
        float v1 = fmaxf(gm[j + 1] * (y1 - g_mu[j + 1]) * g_rstd[j + 1] + bt[j + 1], 0.f);
        h[2 * p] = v0; h[2 * p + 1] = v1;
        ssq += v0 * v0 + v1 * v1;
    }
    float tot = block_sum256(ssq);
    float n = sqrtf(tot);
    float coef = 0.f;
    if (n > 0.f) {
        const float sc = 0.31622776601683794f;
        float th = tanhf(sc * n);
        float s  = 0.9f * th / (sc * n);
        float ny = 0.9f * th / sc;
        float dn = fmaxf(ny, 1e-8f);
        coef = -s * atanhf(sc * dn) / (sc * dn);
    }
    __half* Yh = out + (size_t)row * HH;
    __half* Yl = out + (size_t)Bsz * HH + (size_t)row * HH;
#pragma unroll
    for (int p = 0; p < 4; p++) {
        int j = p * 512 + threadIdx.x * 2;
        float v0 = coef * h[2 * p], v1 = coef * h[2 * p + 1];
        __half2 hp, lp;
        hp.x = __float2half_rn(v0); hp.y = __float2half_rn(v1);
        lp.x = __float2half_rn(v0 - __half2float(hp.x));
        lp.y = __float2half_rn(v1 - __half2float(hp.y));
        *reinterpret_cast<__half2*>(&Yh[j]) = hp;
        *reinterpret_cast<__half2*>(&Yl[j]) = lp;
    }
}

// ---------------- stage 2: BN+relu+exp0+p2e -> fp16 [hi|lo] ------------------
__global__ __launch_bounds__(256)
void rowmap_stage2(const float* __restrict__ act, const float* __restrict__ gm,
                   const float* __restrict__ bt, __half* __restrict__ out) {
    const int row = blockIdx.x;
    float h[8];
    float ssq = 0.f;
#pragma unroll
    for (int p = 0; p < 4; p++) {
        int j = p * 512 + threadIdx.x * 2;
        float y0 = act[(size_t)row * HH + j];
        float y1 = act[(size_t)row * HH + j + 1];
        float v0 = fmaxf(gm[j] * (y0 - g_mu[j]) * g_rstd[j] + bt[j], 0.f);
        float v1 = fmaxf(gm[j + 1] * (y1 - g_mu[j + 1]) * g_rstd[j + 1] + bt[j + 1], 0.f);
        h[2 * p] = v0; h[2 * p + 1] = v1;
        ssq += v0 * v0 + v1 * v1;
    }
    float tot = block_sum256(ssq);
    float n = sqrtf(tot);
    const float sc = 0.31622776601683794f;
    float vn  = fmaxf(n, 1e-8f);
    float scl = tanhf(sc * vn) / (sc * vn);
    float nn  = scl * n;
    float nnc = fminf(fmaxf(nn, 1e-8f), 1.0f);
    float coef = scl * atanhf(sc * nnc) / (sc * nnc);
    __half* Yh = out + (size_t)row * HH;
    __half* Yl = out + (size_t)Bsz * HH + (size_t)row * HH;
#pragma unroll
    for (int p = 0; p < 4; p++) {
        int j = p * 512 + threadIdx.x * 2;
        float v0 = coef * h[2 * p], v1 = coef * h[2 * p + 1];
        __half2 hp, lp;
        hp.x = __float2half_rn(v0); hp.y = __float2half_rn(v1);
        lp.x = __float2half_rn(v0 - __half2float(hp.x));
        lp.y = __float2half_rn(v1 - __half2float(hp.y));
        *reinterpret_cast<__half2*>(&Yh[j]) = hp;
        *reinterpret_cast<__half2*>(&Yl[j]) = lp;
    }
}

// ---------------- log_softmax over 1000 cols ---------------------------------
__global__ __launch_bounds__(256)
void log_softmax_kernel(const float* __restrict__ logits, float* __restrict__ out) {
    const int row = blockIdx.x;
    float x[4];
    float mx = -1e30f;
#pragma unroll
    for (int k = 0; k < 4; k++) {
        int j = k * 256 + threadIdx.x;
        x[k] = (j < DOUT) ? logits[(size_t)row * DOUT + j] : -1e30f;
        mx = fmaxf(mx, x[k]);
    }
    mx = block_max256(mx);
    float se = 0.f;
#pragma unroll
    for (int k = 0; k < 4; k++) {
        int j = k * 256 + threadIdx.x;
        if (j < DOUT) se += expf(x[k] - mx);
    }
    se = block_sum256(se);
    float lse = logf(se);
#pragma unroll
    for (int k = 0; k < 4; k++) {
        int j = k * 256 + threadIdx.x;
        if (j < DOUT) out[(size_t)row * DOUT + j] = x[k] - mx - lse;
    }
}

// ---------------- launcher ----------------------------------------------------
extern "C" void kernel_launch(void* const* d_in, const int* in_sizes, int n_in,
                              void* d_out, int out_size) {
    const float* x   = (const float*)d_in[0];
    const float* W1  = (const float*)d_in[1];
    const float* b1  = (const float*)d_in[2];
    const float* g1  = (const float*)d_in[3];
    const float* be1 = (const float*)d_in[4];
    const float* W2  = (const float*)d_in[5];
    const float* b2  = (const float*)d_in[6];
    const float* g2  = (const float*)d_in[7];
    const float* be2 = (const float*)d_in[8];
    const float* W3  = (const float*)d_in[9];
    const float* b3  = (const float*)d_in[10];
    float* out = (float*)d_out;

    float *act, *logits, *psum, *psq;
    __half *A1, *A2, *Wh1, *Wh2, *Wh3;
    cudaGetSymbolAddress((void**)&act,    g_act);
    cudaGetSymbolAddress((void**)&logits, g_logits);
    cudaGetSymbolAddress((void**)&psum,   g_psumf);
    cudaGetSymbolAddress((void**)&psq,    g_psqf);
    cudaGetSymbolAddress((void**)&A1,     g_A1);
    cudaGetSymbolAddress((void**)&A2,     g_A2);
    cudaGetSymbolAddress((void**)&Wh1,    g_W1);
    cudaGetSymbolAddress((void**)&Wh2,    g_W2);
    cudaGetSymbolAddress((void**)&Wh3,    g_W3);

    cudaFuncSetAttribute(gemm_mma<4, true>,  cudaFuncAttributeMaxDynamicSharedMemorySize, SMEM_TOT);
    cudaFuncSetAttribute(gemm_mma<5, true>,  cudaFuncAttributeMaxDynamicSharedMemorySize, SMEM_TOT);
    cudaFuncSetAttribute(gemm_mma<5, false>, cudaFuncAttributeMaxDynamicSharedMemorySize, SMEM_TOT);

    dim3 blk(256);

    // converts (gemm L1 placed at launch index 3 so the profiler lands on it)
    convert_h<<<HH, blk>>>(W1, Wh1, HH, DIN);
    convert_split<<<Bsz, blk>>>(x, A1, DIN, Bsz);
    convert_h<<<HH, blk>>>(W2, Wh2, HH, HH);

    // Layer 1
    gemm_mma<4, true><<<dim3(HH / 128, Bsz / 128), blk, SMEM_TOT>>>(
        A1, A1 + (size_t)Bsz * DIN, Wh1, b1, act, HH, DIN, psum, psq);
    bn_finalize<<<8, 256>>>();
    rowmap_stage1<<<Bsz, blk>>>(act, g1, be1, A2);
    convert_h<<<1024, blk>>>(W3, Wh3, DOUT, HH);

    // Layer 2
    gemm_mma<5, true><<<dim3(HH / 128, Bsz / 128), blk, SMEM_TOT>>>(
        A2, A2 + (size_t)Bsz * HH, Wh2, b2, act, HH, HH, psum, psq);
    bn_finalize<<<8, 256>>>();
    rowmap_stage2<<<Bsz, blk>>>(act, g2, be2, A2);

    // Layer 3
    gemm_mma<5, false><<<dim3(1024 / 128, Bsz / 128), blk, SMEM_TOT>>>(
        A2, A2 + (size_t)Bsz * HH, Wh3, b3, logits, DOUT, HH, nullptr, nullptr);
    log_softmax_kernel<<<Bsz, blk>>>(logits, out);
}

// round 10
// speedup vs baseline: 1.7883x; 1.1275x over previous
#include <cuda_runtime.h>
#include <cuda_fp16.h>
#include <math.h>
#include <stdint.h>

// Problem dims (fixed by the dataset)
#define Bsz  8192
#define DIN  1024
#define HH   2048
#define DOUT 1000
#define MT   (Bsz / 128)     // 64 m-tiles -> BN partial chunks

// ---------------- scratch (device globals) ----------------------------------
__device__ __align__(256) float  g_act[Bsz * HH];
__device__ __align__(256) float  g_logits[Bsz * DOUT];
__device__ __align__(256) __half g_A1[(size_t)Bsz * DIN];
__device__ __align__(256) __half g_A2[(size_t)Bsz * HH];
__device__ __align__(256) __half g_W1[(size_t)HH * DIN];
__device__ __align__(256) __half g_W2[(size_t)HH * HH];
__device__ __align__(256) __half g_W3[(size_t)1024 * HH];       // rows 1000.. zero
__device__ float g_psumf[MT * HH];
__device__ float g_psqf [MT * HH];
__device__ float g_mu[HH], g_rstd[HH];

// ---------------- helpers -----------------------------------------------------
__device__ __forceinline__ uint32_t smem_to_u32(const void* p) {
    uint32_t a;
    asm("{ .reg .u64 t; cvta.to.shared.u64 t, %1; cvt.u32.u64 %0, t; }" : "=r"(a) : "l"(p));
    return a;
}
#define SW128(off) ((off) ^ (((off) >> 3) & 0x70))

__device__ __forceinline__ void cp_async16(uint32_t daddr, const void* gptr) {
    asm volatile("cp.async.cg.shared.global [%0], [%1], 16;" :: "r"(daddr), "l"(gptr));
}
__device__ __forceinline__ void cp_commit() { asm volatile("cp.async.commit_group;"); }
template <int N>
__device__ __forceinline__ void cp_wait() { asm volatile("cp.async.wait_group %0;" :: "n"(N)); }

__device__ __forceinline__ void ldm_x4(uint32_t* r, uint32_t addr) {
    asm volatile("ldmatrix.sync.aligned.m8n8.x4.shared.b16 {%0,%1,%2,%3}, [%4];"
                 : "=r"(r[0]), "=r"(r[1]), "=r"(r[2]), "=r"(r[3]) : "r"(addr));
}
__device__ __forceinline__ void mma16816(float* d, const uint32_t* a, const uint32_t* b) {
    asm volatile(
        "mma.sync.aligned.m16n8k16.row.col.f32.f16.f16.f32 "
        "{%0,%1,%2,%3}, {%4,%5,%6,%7}, {%8,%9}, {%0,%1,%2,%3};"
        : "+f"(d[0]), "+f"(d[1]), "+f"(d[2]), "+f"(d[3])
        : "r"(a[0]), "r"(a[1]), "r"(a[2]), "r"(a[3]), "r"(b[0]), "r"(b[1]));
}

// ---------------- single-pass fp16 HMMA GEMM (R7 config) ---------------------
// C[M,Nreal] = A[M,K] x B[Npad,K]^T + bias, fp16 in / fp32 accum.
// CTA tile 128x128, BK=64 fp16. 8 warps = 2(M) x 4(N), warp tile 64x32.
// 3-stage cp.async pipeline, 2 CTAs/SM. Epilogue optionally emits per-column
// BN sum/sumsq partials (deterministic, no atomics).
static constexpr int TILE_BYTES = 128 * 128;              // 16 KB (A or B, one stage)
static constexpr int SMEM_TOT   = 6 * TILE_BYTES + 1024;  // 3 stages x (A+B)

template <int NC, bool STATS>
__global__ void __launch_bounds__(256, 2)
gemm_mma(const __half* __restrict__ A, const __half* __restrict__ B,
         const float* __restrict__ bias, float* __restrict__ C,
         int Nreal, int Kreal, float* __restrict__ psum, float* __restrict__ psq) {
    extern __shared__ uint8_t smem_raw[];
    uint32_t sb = smem_to_u32(smem_raw);
    sb = (sb + 1023) & ~1023u;

    const int tid  = threadIdx.x;
    const int wid  = tid >> 5, lane = tid & 31;
    const int m0   = blockIdx.y * 128, n0 = blockIdx.x * 128;
    const int wM   = wid >> 2;          // 0..1 -> 64-row slab
    const int wN   = wid & 3;           // 0..3 -> 32-col slab

    auto prefetch = [&](int c, int st) {
        const int k0 = c * 64;
        const uint32_t baseA = sb + (uint32_t)st * 2 * TILE_BYTES;
        const uint32_t baseB = baseA + TILE_BYTES;
#pragma unroll
        for (int i = 0; i < 4; i++) {
            int slot = tid + i * 256;
            int row = slot >> 3, s16 = slot & 7;
            uint32_t so = SW128((uint32_t)(row * 128 + s16 * 16));
            cp_async16(baseA + so, A + (size_t)(m0 + row) * Kreal + k0 + s16 * 8);
            cp_async16(baseB + so, B + (size_t)(n0 + row) * Kreal + k0 + s16 * 8);
        }
        cp_commit();
    };

    float acc[4][4][4];
#pragma unroll
    for (int i = 0; i < 4; i++)
#pragma unroll
        for (int j = 0; j < 4; j++)
#pragma unroll
            for (int q = 0; q < 4; q++) acc[i][j][q] = 0.f;

    const int aRow = wM * 64 + (lane & 15);
    const int aCol = ((lane >> 4) & 1) * 16;
    const int bRow = wN * 32 + (lane & 7) + ((lane >> 4) & 1) * 8;
    const int bCol = ((lane >> 3) & 1) * 16;

    prefetch(0, 0);
    prefetch(1, 1);

    int st = 0;
    for (int c = 0; c < NC; c++) {
        if (c + 1 < NC) cp_wait<1>(); else cp_wait<0>();
        __syncthreads();
        if (c + 2 < NC) {
            int st2 = st + 2; if (st2 >= 3) st2 -= 3;
            prefetch(c + 2, st2);
        }

        const uint32_t bufA = sb + (uint32_t)st * 2 * TILE_BYTES;
        const uint32_t bufB = bufA + TILE_BYTES;
#pragma unroll
        for (int s = 0; s < 4; s++) {
            uint32_t afr[4][4];
#pragma unroll
            for (int mi = 0; mi < 4; mi++) {
                uint32_t addr = bufA + SW128((uint32_t)((aRow + mi * 16) * 128 + s * 32 + aCol));
                ldm_x4(afr[mi], addr);
            }
            uint32_t bfr[4][2];
#pragma unroll
            for (int nh = 0; nh < 2; nh++) {
                uint32_t r[4];
                uint32_t addr = bufB + SW128((uint32_t)((bRow + nh * 16) * 128 + s * 32 + bCol));
                ldm_x4(r, addr);
                bfr[nh * 2][0] = r[0]; bfr[nh * 2][1] = r[1];
                bfr[nh * 2 + 1][0] = r[2]; bfr[nh * 2 + 1][1] = r[3];
            }
#pragma unroll
            for (int mi = 0; mi < 4; mi++)
#pragma unroll
                for (int ni = 0; ni < 4; ni++)
                    mma16816(acc[mi][ni], afr[mi], bfr[ni]);
        }
        if (++st == 3) st = 0;
    }

    // epilogue: bias + store + optional per-column stats partials
    float s8[8], q8[8];
    if (STATS) {
#pragma unroll
        for (int i = 0; i < 8; i++) { s8[i] = 0.f; q8[i] = 0.f; }
    }
#pragma unroll
    for (int mi = 0; mi < 4; mi++) {
        const int row = m0 + wM * 64 + mi * 16 + (lane >> 2);
#pragma unroll
        for (int ni = 0; ni < 4; ni++) {
            const int col = n0 + wN * 32 + ni * 8 + (lane & 3) * 2;
            if (col < Nreal) {
                const float b0 = bias[col], b1 = bias[col + 1];
                float v00 = acc[mi][ni][0] + b0, v01 = acc[mi][ni][1] + b1;
                float v10 = acc[mi][ni][2] + b0, v11 = acc[mi][ni][3] + b1;
                *reinterpret_cast<float2*>(&C[(size_t)row * Nreal + col]) = make_float2(v00, v01);
                *reinterpret_cast<float2*>(&C[(size_t)(row + 8) * Nreal + col]) = make_float2(v10, v11);
                if (STATS) {
                    s8[ni * 2]     += v00 + v10;
                    s8[ni * 2 + 1] += v01 + v11;
                    q8[ni * 2]     += v00 * v00 + v10 * v10;
                    q8[ni * 2 + 1] += v01 * v01 + v11 * v11;
                }
            }
        }
    }

    if (STATS) {
        // reduce over the 8 lanes sharing a column (lane>>2 varies, lane&3 fixed)
#pragma unroll
        for (int o = 16; o >= 4; o >>= 1)
#pragma unroll
            for (int i = 0; i < 8; i++) {
                s8[i] += __shfl_xor_sync(0xffffffffu, s8[i], o);
                q8[i] += __shfl_xor_sync(0xffffffffu, q8[i], o);
            }
        __syncthreads();                  // stage buffers now safe to reuse
        float* sred = reinterpret_cast<float*>(smem_raw);      // [2][128]
        float* qred = sred + 256;                              // [2][128]
        if (lane < 4) {
#pragma unroll
            for (int i = 0; i < 8; i++) {
                int colT = wN * 32 + (i >> 1) * 8 + lane * 2 + (i & 1);
                sred[wM * 128 + colT] = s8[i];
                qred[wM * 128 + colT] = q8[i];
            }
        }
        __syncthreads();
        if (tid < 128) {
            const int mt = blockIdx.y;
            psum[(size_t)mt * Nreal + n0 + tid] = sred[tid] + sred[128 + tid];
            psq [(size_t)mt * Nreal + n0 + tid] = qred[tid] + qred[128 + tid];
        }
    }
}

// ---------------- fp16 conversion (zero-pad rows beyond R) -------------------
__global__ __launch_bounds__(256)
void convert_h(const float* __restrict__ X, __half* __restrict__ Y, int R, int K) {
    const int r = blockIdx.x;
    __half* Yr = Y + (size_t)r * K;
    if (r >= R) {
        __half2 z; z.x = __float2half(0.f); z.y = z.x;
        for (int j = threadIdx.x * 2; j < K; j += 512)
            *reinterpret_cast<__half2*>(&Yr[j]) = z;
        return;
    }
    for (int j = threadIdx.x * 2; j < K; j += 512) {
        __half2 hp;
        hp.x = __float2half_rn(X[(size_t)r * K + j]);
        hp.y = __float2half_rn(X[(size_t)r * K + j + 1]);
        *reinterpret_cast<__half2*>(&Yr[j]) = hp;
    }
}

// ---------------- BN finalize (64 fp32 partials -> mu/rstd, double) ----------
__global__ void bn_finalize() {
    int j = blockIdx.x * blockDim.x + threadIdx.x;
    if (j >= HH) return;
    double s = 0.0, ss = 0.0;
    for (int c = 0; c < MT; c++) {
        s  += (double)g_psumf[(size_t)c * HH + j];
        ss += (double)g_psqf [(size_t)c * HH + j];
    }
    double mu  = s / (double)Bsz;
    double var = ss / (double)Bsz - mu * mu;
    g_mu[j]   = (float)mu;
    g_rstd[j] = (float)(1.0 / sqrt(var + 1e-5));
}

// ---------------- block reductions -------------------------------------------
__device__ __forceinline__ float block_sum256(float v) {
#pragma unroll
    for (int o = 16; o > 0; o >>= 1) v += __shfl_down_sync(0xffffffffu, v, o);
    __shared__ float sh[9];
    int w = threadIdx.x >> 5, l = threadIdx.x & 31;
    if (l == 0) sh[w] = v;
    __syncthreads();
    if (threadIdx.x == 0) {
        float t = 0.f;
#pragma unroll
        for (int q = 0; q < 8; q++) t += sh[q];
        sh[8] = t;
    }
    __syncthreads();
    return sh[8];
}
__device__ __forceinline__ float block_max256(float v) {
#pragma unroll
    for (int o = 16; o > 0; o >>= 1) v = fmaxf(v, __shfl_down_sync(0xffffffffu, v, o));
    __shared__ float sh[9];
    int w = threadIdx.x >> 5, l = threadIdx.x & 31;
    if (l == 0) sh[w] = v;
    __syncthreads();
    if (threadIdx.x == 0) {
        float t = sh[0];
#pragma unroll
        for (int q = 1; q < 8; q++) t = fmaxf(t, sh[q]);
        sh[8] = t;
    }
    __syncthreads();
    return sh[8];
}

// ---------------- stage 1: BN+relu+e2p+log0 -> fp16 --------------------------
__global__ __launch_bounds__(256)
void rowmap_stage1(const float* __restrict__ act, const float* __restrict__ gm,
                   const float* __restrict__ bt, __half* __restrict__ out) {
    const int row = blockIdx.x;
    float h[8];
    float ssq = 0.f;
#pragma unroll
    for (int p = 0; p < 4; p++) {
        int j = p * 512 + threadIdx.x * 2;
        float y0 = act[(size_t)row * HH + j];
        float y1 = act[(size_t)row * HH + j + 1];
        float v0 = fmaxf(gm[j] * (y0 - g_mu[j]) * g_rstd[j] + bt[j], 0.f);
        float v1 = fmaxf(gm[j + 1] * (y1 - g_mu[j + 1]) * g_rstd[j + 1] + bt[j + 1], 0.f);
        h[2 * p] = v0; h[2 * p + 1] = v1;
        ssq += v0 * v0 + v1 * v1;
    }
    float tot = block_sum256(ssq);
    float n = sqrtf(tot);
    float coef = 0.f;
    if (n > 0.f) {
        const float sc = 0.31622776601683794f;
        float th = tanhf(sc * n);
        float s  = 0.9f * th / (sc * n);
        float ny = 0.9f * th / sc;
        float dn = fmaxf(ny, 1e-8f);
        coef = -s * atanhf(sc * dn) / (sc * dn);
    }
    __half* Yr = out + (size_t)row * HH;
#pragma unroll
    for (int p = 0; p < 4; p++) {
        int j = p * 512 + threadIdx.x * 2;
        __half2 hp;
        hp.x = __float2half_rn(coef * h[2 * p]);
        hp.y = __float2half_rn(coef * h[2 * p + 1]);
        *reinterpret_cast<__half2*>(&Yr[j]) = hp;
    }
}

// ---------------- stage 2: BN+relu+exp0+p2e -> fp16 --------------------------
__global__ __launch_bounds__(256)
void rowmap_stage2(const float* __restrict__ act, const float* __restrict__ gm,
                   const float* __restrict__ bt, __half* __restrict__ out) {
    const int row = blockIdx.x;
    float h[8];
    float ssq = 0.f;
#pragma unroll
    for (int p = 0; p < 4; p++) {
        int j = p * 512 + threadIdx.x * 2;
        float y0 = act[(size_t)row * HH + j];
        float y1 = act[(size_t)row * HH + j + 1];
        float v0 = fmaxf(gm[j] * (y0 - g_mu[j]) * g_rstd[j] + bt[j], 0.f);
        float v1 = fmaxf(gm[j + 1] * (y1 - g_mu[j + 1]) * g_rstd[j + 1] + bt[j + 1], 0.f);
        h[2 * p] = v0; h[2 * p + 1] = v1;
        ssq += v0 * v0 + v1 * v1;
    }
    float tot = block_sum256(ssq);
    float n = sqrtf(tot);
    const float sc = 0.31622776601683794f;
    float vn  = fmaxf(n, 1e-8f);
    float scl = tanhf(sc * vn) / (sc * vn);
    float nn  = scl * n;
    float nnc = fminf(fmaxf(nn, 1e-8f), 1.0f);
    float coef = scl * atanhf(sc * nnc) / (sc * nnc);
    __half* Yr = out + (size_t)row * HH;
#pragma unroll
    for (int p = 0; p < 4; p++) {
        int j = p * 512 + threadIdx.x * 2;
        __half2 hp;
        hp.x = __float2half_rn(coef * h[2 * p]);
        hp.y = __float2half_rn(coef * h[2 * p + 1]);
        *reinterpret_cast<__half2*>(&Yr[j]) = hp;
    }
}

// ---------------- log_softmax over 1000 cols ---------------------------------
__global__ __launch_bounds__(256)
void log_softmax_kernel(const float* __restrict__ logits, float* __restrict__ out) {
    const int row = blockIdx.x;
    float x[4];
    float mx = -1e30f;
#pragma unroll
    for (int k = 0; k < 4; k++) {
        int j = k * 256 + threadIdx.x;
        x[k] = (j < DOUT) ? logits[(size_t)row * DOUT + j] : -1e30f;
        mx = fmaxf(mx, x[k]);
    }
    mx = block_max256(mx);
    float se = 0.f;
#pragma unroll
    for (int k = 0; k < 4; k++) {
        int j = k * 256 + threadIdx.x;
        if (j < DOUT) se += expf(x[k] - mx);
    }
    se = block_sum256(se);
    float lse = logf(se);
#pragma unroll
    for (int k = 0; k < 4; k++) {
        int j = k * 256 + threadIdx.x;
        if (j < DOUT) out[(size_t)row * DOUT + j] = x[k] - mx - lse;
    }
}

// ---------------- launcher ----------------------------------------------------
extern "C" void kernel_launch(void* const* d_in, const int* in_sizes, int n_in,
                              void* d_out, int out_size) {
    const float* x   = (const float*)d_in[0];
    const float* W1  = (const float*)d_in[1];
    const float* b1  = (const float*)d_in[2];
    const float* g1  = (const float*)d_in[3];
    const float* be1 = (const float*)d_in[4];
    const float* W2  = (const float*)d_in[5];
    const float* b2  = (const float*)d_in[6];
    const float* g2  = (const float*)d_in[7];
    const float* be2 = (const float*)d_in[8];
    const float* W3  = (const float*)d_in[9];
    const float* b3  = (const float*)d_in[10];
    float* out = (float*)d_out;

    float *act, *logits, *psum, *psq;
    __half *A1, *A2, *Wh1, *Wh2, *Wh3;
    cudaGetSymbolAddress((void**)&act,    g_act);
    cudaGetSymbolAddress((void**)&logits, g_logits);
    cudaGetSymbolAddress((void**)&psum,   g_psumf);
    cudaGetSymbolAddress((void**)&psq,    g_psqf);
    cudaGetSymbolAddress((void**)&A1,     g_A1);
    cudaGetSymbolAddress((void**)&A2,     g_A2);
    cudaGetSymbolAddress((void**)&Wh1,    g_W1);
    cudaGetSymbolAddress((void**)&Wh2,    g_W2);
    cudaGetSymbolAddress((void**)&Wh3,    g_W3);

    cudaFuncSetAttribute(gemm_mma<16, true>,  cudaFuncAttributeMaxDynamicSharedMemorySize, SMEM_TOT);
    cudaFuncSetAttribute(gemm_mma<32, true>,  cudaFuncAttributeMaxDynamicSharedMemorySize, SMEM_TOT);
    cudaFuncSetAttribute(gemm_mma<32, false>, cudaFuncAttributeMaxDynamicSharedMemorySize, SMEM_TOT);

    dim3 blk(256);

    // converts (gemm L1 placed at launch index 3 so the profiler lands on it)
    convert_h<<<HH, blk>>>(W1, Wh1, HH, DIN);
    convert_h<<<Bsz, blk>>>(x, A1, Bsz, DIN);
    convert_h<<<HH, blk>>>(W2, Wh2, HH, HH);

    // Layer 1 (K=1024 -> 16 chunks)
    gemm_mma<16, true><<<dim3(HH / 128, Bsz / 128), blk, SMEM_TOT>>>(
        A1, Wh1, b1, act, HH, DIN, psum, psq);
    bn_finalize<<<8, 256>>>();
    rowmap_stage1<<<Bsz, blk>>>(act, g1, be1, A2);
    convert_h<<<1024, blk>>>(W3, Wh3, DOUT, HH);

    // Layer 2 (K=2048 -> 32 chunks)
    gemm_mma<32, true><<<dim3(HH / 128, Bsz / 128), blk, SMEM_TOT>>>(
        A2, Wh2, b2, act, HH, HH, psum, psq);
    bn_finalize<<<8, 256>>>();
    rowmap_stage2<<<Bsz, blk>>>(act, g2, be2, A2);

    // Layer 3 (K=2048 -> 32 chunks)
    gemm_mma<32, false><<<dim3(1024 / 128, Bsz / 128), blk, SMEM_TOT>>>(
        A2, Wh3, b3, logits, DOUT, HH, nullptr, nullptr);
    log_softmax_kernel<<<Bsz, blk>>>(logits, out);
}

// round 11
// speedup vs baseline: 2.8230x; 1.5786x over previous
#include <cuda_runtime.h>
#include <cuda_fp16.h>
#include <math.h>
#include <stdint.h>

// Problem dims (fixed by the dataset)
#define Bsz  8192
#define DIN  1024
#define HH   2048
#define DOUT 1000
#define MT   (Bsz / 128)     // 64 m-tiles -> BN partial chunks

// ---------------- scratch (device globals) ----------------------------------
__device__ __align__(256) __half g_act[(size_t)Bsz * HH];       // fp16 activations
__device__ __align__(256) float  g_logits[Bsz * DOUT];
__device__ __align__(256) __half g_A1[(size_t)Bsz * DIN];
__device__ __align__(256) __half g_A2[(size_t)Bsz * HH];
__device__ __align__(256) __half g_W1[(size_t)HH * DIN];
__device__ __align__(256) __half g_W2[(size_t)HH * HH];
__device__ __align__(256) __half g_W3[(size_t)1024 * HH];       // rows 1000.. zero
__device__ float g_psumf[MT * HH];
__device__ float g_psqf [MT * HH];
__device__ float g_scale[HH], g_shift[HH];                      // fused BN affine

// ---------------- helpers -----------------------------------------------------
__device__ __forceinline__ uint32_t smem_to_u32(const void* p) {
    uint32_t a;
    asm("{ .reg .u64 t; cvta.to.shared.u64 t, %1; cvt.u32.u64 %0, t; }" : "=r"(a) : "l"(p));
    return a;
}
#define SW128(off) ((off) ^ (((off) >> 3) & 0x70))

__device__ __forceinline__ void cp_async16(uint32_t daddr, const void* gptr) {
    asm volatile("cp.async.cg.shared.global [%0], [%1], 16;" :: "r"(daddr), "l"(gptr));
}
__device__ __forceinline__ void cp_commit() { asm volatile("cp.async.commit_group;"); }
template <int N>
__device__ __forceinline__ void cp_wait() { asm volatile("cp.async.wait_group %0;" :: "n"(N)); }

__device__ __forceinline__ void ldm_x4(uint32_t* r, uint32_t addr) {
    asm volatile("ldmatrix.sync.aligned.m8n8.x4.shared.b16 {%0,%1,%2,%3}, [%4];"
                 : "=r"(r[0]), "=r"(r[1]), "=r"(r[2]), "=r"(r[3]) : "r"(addr));
}
__device__ __forceinline__ void mma16816(float* d, const uint32_t* a, const uint32_t* b) {
    asm volatile(
        "mma.sync.aligned.m16n8k16.row.col.f32.f16.f16.f32 "
        "{%0,%1,%2,%3}, {%4,%5,%6,%7}, {%8,%9}, {%0,%1,%2,%3};"
        : "+f"(d[0]), "+f"(d[1]), "+f"(d[2]), "+f"(d[3])
        : "r"(a[0]), "r"(a[1]), "r"(a[2]), "r"(a[3]), "r"(b[0]), "r"(b[1]));
}

// typed pair-store: float -> float2, __half -> half2
__device__ __forceinline__ void store2(float* C, size_t idx, float v0, float v1) {
    *reinterpret_cast<float2*>(&C[idx]) = make_float2(v0, v1);
}
__device__ __forceinline__ void store2(__half* C, size_t idx, float v0, float v1) {
    *reinterpret_cast<__half2*>(&C[idx]) = __floats2half2_rn(v0, v1);
}

// ---------------- single-pass fp16 HMMA GEMM (R7 config) ---------------------
// C[M,Nreal] = A[M,K] x B[Npad,K]^T + bias, fp16 in / fp32 accum, CT out.
// CTA tile 128x128, BK=64 fp16. 8 warps = 2(M) x 4(N), warp tile 64x32.
// 3-stage cp.async pipeline, 2 CTAs/SM. Epilogue optionally emits per-column
// BN sum/sumsq partials (deterministic, no atomics) from the fp32 values.
static constexpr int TILE_BYTES = 128 * 128;              // 16 KB (A or B, one stage)
static constexpr int SMEM_TOT   = 6 * TILE_BYTES + 1024;  // 3 stages x (A+B)

template <int NC, bool STATS, typename CT>
__global__ void __launch_bounds__(256, 2)
gemm_mma(const __half* __restrict__ A, const __half* __restrict__ B,
         const float* __restrict__ bias, CT* __restrict__ C,
         int Nreal, int Kreal, float* __restrict__ psum, float* __restrict__ psq) {
    extern __shared__ uint8_t smem_raw[];
    uint32_t sb = smem_to_u32(smem_raw);
    sb = (sb + 1023) & ~1023u;

    const int tid  = threadIdx.x;
    const int wid  = tid >> 5, lane = tid & 31;
    const int m0   = blockIdx.y * 128, n0 = blockIdx.x * 128;
    const int wM   = wid >> 2;          // 0..1 -> 64-row slab
    const int wN   = wid & 3;           // 0..3 -> 32-col slab

    auto prefetch = [&](int c, int st) {
        const int k0 = c * 64;
        const uint32_t baseA = sb + (uint32_t)st * 2 * TILE_BYTES;
        const uint32_t baseB = baseA + TILE_BYTES;
#pragma unroll
        for (int i = 0; i < 4; i++) {
            int slot = tid + i * 256;
            int row = slot >> 3, s16 = slot & 7;
            uint32_t so = SW128((uint32_t)(row * 128 + s16 * 16));
            cp_async16(baseA + so, A + (size_t)(m0 + row) * Kreal + k0 + s16 * 8);
            cp_async16(baseB + so, B + (size_t)(n0 + row) * Kreal + k0 + s16 * 8);
        }
        cp_commit();
    };

    float acc[4][4][4];
#pragma unroll
    for (int i = 0; i < 4; i++)
#pragma unroll
        for (int j = 0; j < 4; j++)
#pragma unroll
            for (int q = 0; q < 4; q++) acc[i][j][q] = 0.f;

    const int aRow = wM * 64 + (lane & 15);
    const int aCol = ((lane >> 4) & 1) * 16;
    const int bRow = wN * 32 + (lane & 7) + ((lane >> 4) & 1) * 8;
    const int bCol = ((lane >> 3) & 1) * 16;

    prefetch(0, 0);
    prefetch(1, 1);

    int st = 0;
    for (int c = 0; c < NC; c++) {
        if (c + 1 < NC) cp_wait<1>(); else cp_wait<0>();
        __syncthreads();
        if (c + 2 < NC) {
            int st2 = st + 2; if (st2 >= 3) st2 -= 3;
            prefetch(c + 2, st2);
        }

        const uint32_t bufA = sb + (uint32_t)st * 2 * TILE_BYTES;
        const uint32_t bufB = bufA + TILE_BYTES;
#pragma unroll
        for (int s = 0; s < 4; s++) {
            uint32_t afr[4][4];
#pragma unroll
            for (int mi = 0; mi < 4; mi++) {
                uint32_t addr = bufA + SW128((uint32_t)((aRow + mi * 16) * 128 + s * 32 + aCol));
                ldm_x4(afr[mi], addr);
            }
            uint32_t bfr[4][2];
#pragma unroll
            for (int nh = 0; nh < 2; nh++) {
                uint32_t r[4];
                uint32_t addr = bufB + SW128((uint32_t)((bRow + nh * 16) * 128 + s * 32 + bCol));
                ldm_x4(r, addr);
                bfr[nh * 2][0] = r[0]; bfr[nh * 2][1] = r[1];
                bfr[nh * 2 + 1][0] = r[2]; bfr[nh * 2 + 1][1] = r[3];
            }
#pragma unroll
            for (int mi = 0; mi < 4; mi++)
#pragma unroll
                for (int ni = 0; ni < 4; ni++)
                    mma16816(acc[mi][ni], afr[mi], bfr[ni]);
        }
        if (++st == 3) st = 0;
    }

    // epilogue: bias + store + optional per-column stats partials
    float s8[8], q8[8];
    if (STATS) {
#pragma unroll
        for (int i = 0; i < 8; i++) { s8[i] = 0.f; q8[i] = 0.f; }
    }
#pragma unroll
    for (int mi = 0; mi < 4; mi++) {
        const int row = m0 + wM * 64 + mi * 16 + (lane >> 2);
#pragma unroll
        for (int ni = 0; ni < 4; ni++) {
            const int col = n0 + wN * 32 + ni * 8 + (lane & 3) * 2;
            if (col < Nreal) {
                const float b0 = bias[col], b1 = bias[col + 1];
                float v00 = acc[mi][ni][0] + b0, v01 = acc[mi][ni][1] + b1;
                float v10 = acc[mi][ni][2] + b0, v11 = acc[mi][ni][3] + b1;
                store2(C, (size_t)row * Nreal + col, v00, v01);
                store2(C, (size_t)(row + 8) * Nreal + col, v10, v11);
                if (STATS) {
                    s8[ni * 2]     += v00 + v10;
                    s8[ni * 2 + 1] += v01 + v11;
                    q8[ni * 2]     += v00 * v00 + v10 * v10;
                    q8[ni * 2 + 1] += v01 * v01 + v11 * v11;
                }
            }
        }
    }

    if (STATS) {
        // reduce over the 8 lanes sharing a column (lane>>2 varies, lane&3 fixed)
#pragma unroll
        for (int o = 16; o >= 4; o >>= 1)
#pragma unroll
            for (int i = 0; i < 8; i++) {
                s8[i] += __shfl_xor_sync(0xffffffffu, s8[i], o);
                q8[i] += __shfl_xor_sync(0xffffffffu, q8[i], o);
            }
        __syncthreads();                  // stage buffers now safe to reuse
        float* sred = reinterpret_cast<float*>(smem_raw);      // [2][128]
        float* qred = sred + 256;                              // [2][128]
        if (lane < 4) {
#pragma unroll
            for (int i = 0; i < 8; i++) {
                int colT = wN * 32 + (i >> 1) * 8 + lane * 2 + (i & 1);
                sred[wM * 128 + colT] = s8[i];
                qred[wM * 128 + colT] = q8[i];
            }
        }
        __syncthreads();
        if (tid < 128) {
            const int mt = blockIdx.y;
            psum[(size_t)mt * Nreal + n0 + tid] = sred[tid] + sred[128 + tid];
            psq [(size_t)mt * Nreal + n0 + tid] = qred[tid] + qred[128 + tid];
        }
    }
}

// ---------------- fp16 conversion (zero-pad rows beyond R) -------------------
__global__ __launch_bounds__(256)
void convert_h(const float* __restrict__ X, __half* __restrict__ Y, int R, int K) {
    const int r = blockIdx.x;
    __half* Yr = Y + (size_t)r * K;
    if (r >= R) {
        __half2 z; z.x = __float2half(0.f); z.y = z.x;
        for (int j = threadIdx.x * 2; j < K; j += 512)
            *reinterpret_cast<__half2*>(&Yr[j]) = z;
        return;
    }
    for (int j = threadIdx.x * 2; j < K; j += 512) {
        float2 v = *reinterpret_cast<const float2*>(&X[(size_t)r * K + j]);
        *reinterpret_cast<__half2*>(&Yr[j]) = __floats2half2_rn(v.x, v.y);
    }
}

// ---------------- BN finalize: partials -> fused scale/shift (double) --------
__global__ void bn_finalize(const float* __restrict__ gm, const float* __restrict__ bt) {
    int j = blockIdx.x * blockDim.x + threadIdx.x;
    if (j >= HH) return;
    double s = 0.0, ss = 0.0;
    for (int c = 0; c < MT; c++) {
        s  += (double)g_psumf[(size_t)c * HH + j];
        ss += (double)g_psqf [(size_t)c * HH + j];
    }
    double mu  = s / (double)Bsz;
    double var = ss / (double)Bsz - mu * mu;
    float rstd = (float)(1.0 / sqrt(var + 1e-5));
    float sc = gm[j] * rstd;
    g_scale[j] = sc;
    g_shift[j] = bt[j] - (float)mu * sc;
}

// ---------------- block reductions -------------------------------------------
__device__ __forceinline__ float block_sum256(float v) {
#pragma unroll
    for (int o = 16; o > 0; o >>= 1) v += __shfl_down_sync(0xffffffffu, v, o);
    __shared__ float sh[9];
    int w = threadIdx.x >> 5, l = threadIdx.x & 31;
    if (l == 0) sh[w] = v;
    __syncthreads();
    if (threadIdx.x == 0) {
        float t = 0.f;
#pragma unroll
        for (int q = 0; q < 8; q++) t += sh[q];
        sh[8] = t;
    }
    __syncthreads();
    return sh[8];
}
__device__ __forceinline__ float block_max256(float v) {
#pragma unroll
    for (int o = 16; o > 0; o >>= 1) v = fmaxf(v, __shfl_down_sync(0xffffffffu, v, o));
    __shared__ float sh[9];
    int w = threadIdx.x >> 5, l = threadIdx.x & 31;
    if (l == 0) sh[w] = v;
    __syncthreads();
    if (threadIdx.x == 0) {
        float t = sh[0];
#pragma unroll
        for (int q = 1; q < 8; q++) t = fmaxf(t, sh[q]);
        sh[8] = t;
    }
    __syncthreads();
    return sh[8];
}

// ---------------- stage 1: BN+relu+e2p+log0 -> fp16 --------------------------
__global__ __launch_bounds__(256)
void rowmap_stage1(const __half* __restrict__ act, __half* __restrict__ out) {
    const int row = blockIdx.x;
    float h[8];
    float ssq = 0.f;
#pragma unroll
    for (int p = 0; p < 4; p++) {
        int j = p * 512 + threadIdx.x * 2;
        __half2 y2 = *reinterpret_cast<const __half2*>(&act[(size_t)row * HH + j]);
        float y0 = __half2float(y2.x), y1 = __half2float(y2.y);
        float v0 = fmaxf(fmaf(g_scale[j], y0, g_shift[j]), 0.f);
        float v1 = fmaxf(fmaf(g_scale[j + 1], y1, g_shift[j + 1]), 0.f);
        h[2 * p] = v0; h[2 * p + 1] = v1;
        ssq += v0 * v0 + v1 * v1;
    }
    float tot = block_sum256(ssq);
    float n = sqrtf(tot);
    float coef = 0.f;
    if (n > 0.f) {
        const float sc = 0.31622776601683794f;
        float th = tanhf(sc * n);
        float s  = 0.9f * th / (sc * n);
        float ny = 0.9f * th / sc;
        float dn = fmaxf(ny, 1e-8f);
        coef = -s * atanhf(sc * dn) / (sc * dn);
    }
    __half* Yr = out + (size_t)row * HH;
#pragma unroll
    for (int p = 0; p < 4; p++) {
        int j = p * 512 + threadIdx.x * 2;
        *reinterpret_cast<__half2*>(&Yr[j]) =
            __floats2half2_rn(coef * h[2 * p], coef * h[2 * p + 1]);
    }
}

// ---------------- stage 2: BN+relu+exp0+p2e -> fp16 --------------------------
__global__ __launch_bounds__(256)
void rowmap_stage2(const __half* __restrict__ act, __half* __restrict__ out) {
    const int row = blockIdx.x;
    float h[8];
    float ssq = 0.f;
#pragma unroll
    for (int p = 0; p < 4; p++) {
        int j = p * 512 + threadIdx.x * 2;
        __half2 y2 = *reinterpret_cast<const __half2*>(&act[(size_t)row * HH + j]);
        float y0 = __half2float(y2.x), y1 = __half2float(y2.y);
        float v0 = fmaxf(fmaf(g_scale[j], y0, g_shift[j]), 0.f);
        float v1 = fmaxf(fmaf(g_scale[j + 1], y1, g_shift[j + 1]), 0.f);
        h[2 * p] = v0; h[2 * p + 1] = v1;
        ssq += v0 * v0 + v1 * v1;
    }
    float tot = block_sum256(ssq);
    float n = sqrtf(tot);
    const float sc = 0.31622776601683794f;
    float vn  = fmaxf(n, 1e-8f);
    float scl = tanhf(sc * vn) / (sc * vn);
    float nn  = scl * n;
    float nnc = fminf(fmaxf(nn, 1e-8f), 1.0f);
    float coef = scl * atanhf(sc * nnc) / (sc * nnc);
    __half* Yr = out + (size_t)row * HH;
#pragma unroll
    for (int p = 0; p < 4; p++) {
        int j = p * 512 + threadIdx.x * 2;
        *reinterpret_cast<__half2*>(&Yr[j]) =
            __floats2half2_rn(coef * h[2 * p], coef * h[2 * p + 1]);
    }
}

// ---------------- log_softmax over 1000 cols ---------------------------------
__global__ __launch_bounds__(256)
void log_softmax_kernel(const float* __restrict__ logits, float* __restrict__ out) {
    const int row = blockIdx.x;
    float x[4];
    float mx = -1e30f;
#pragma unroll
    for (int k = 0; k < 4; k++) {
        int j = k * 256 + threadIdx.x;
        x[k] = (j < DOUT) ? logits[(size_t)row * DOUT + j] : -1e30f;
        mx = fmaxf(mx, x[k]);
    }
    mx = block_max256(mx);
    float se = 0.f;
#pragma unroll
    for (int k = 0; k < 4; k++) {
        int j = k * 256 + threadIdx.x;
        if (j < DOUT) se += expf(x[k] - mx);
    }
    se = block_sum256(se);
    float lse = logf(se);
#pragma unroll
    for (int k = 0; k < 4; k++) {
        int j = k * 256 + threadIdx.x;
        if (j < DOUT) out[(size_t)row * DOUT + j] = x[k] - mx - lse;
    }
}

// ---------------- launcher ----------------------------------------------------
extern "C" void kernel_launch(void* const* d_in, const int* in_sizes, int n_in,
                              void* d_out, int out_size) {
    const float* x   = (const float*)d_in[0];
    const float* W1  = (const float*)d_in[1];
    const float* b1  = (const float*)d_in[2];
    const float* g1  = (const float*)d_in[3];
    const float* be1 = (const float*)d_in[4];
    const float* W2  = (const float*)d_in[5];
    const float* b2  = (const float*)d_in[6];
    const float* g2  = (const float*)d_in[7];
    const float* be2 = (const float*)d_in[8];
    const float* W3  = (const float*)d_in[9];
    const float* b3  = (const float*)d_in[10];
    float* out = (float*)d_out;

    float *logits, *psum, *psq;
    __half *act, *A1, *A2, *Wh1, *Wh2, *Wh3;
    cudaGetSymbolAddress((void**)&act,    g_act);
    cudaGetSymbolAddress((void**)&logits, g_logits);
    cudaGetSymbolAddress((void**)&psum,   g_psumf);
    cudaGetSymbolAddress((void**)&psq,    g_psqf);
    cudaGetSymbolAddress((void**)&A1,     g_A1);
    cudaGetSymbolAddress((void**)&A2,     g_A2);
    cudaGetSymbolAddress((void**)&Wh1,    g_W1);
    cudaGetSymbolAddress((void**)&Wh2,    g_W2);
    cudaGetSymbolAddress((void**)&Wh3,    g_W3);

    cudaFuncSetAttribute((const void*)gemm_mma<16, true,  __half>, cudaFuncAttributeMaxDynamicSharedMemorySize, SMEM_TOT);
    cudaFuncSetAttribute((const void*)gemm_mma<32, true,  __half>, cudaFuncAttributeMaxDynamicSharedMemorySize, SMEM_TOT);
    cudaFuncSetAttribute((const void*)gemm_mma<32, false, float>,  cudaFuncAttributeMaxDynamicSharedMemorySize, SMEM_TOT);

    dim3 blk(256);

    // converts (gemm L1 placed at launch index 3 so the profiler lands on it)
    convert_h<<<HH, blk>>>(W1, Wh1, HH, DIN);
    convert_h<<<Bsz, blk>>>(x, A1, Bsz, DIN);
    convert_h<<<HH, blk>>>(W2, Wh2, HH, HH);

    // Layer 1 (K=1024 -> 16 chunks)
    gemm_mma<16, true, __half><<<dim3(HH / 128, Bsz / 128), blk, SMEM_TOT>>>(
        A1, Wh1, b1, act, HH, DIN, psum, psq);
    bn_finalize<<<8, 256>>>(g1, be1);
    rowmap_stage1<<<Bsz, blk>>>(act, A2);
    convert_h<<<1024, blk>>>(W3, Wh3, DOUT, HH);

    // Layer 2 (K=2048 -> 32 chunks)
    gemm_mma<32, true, __half><<<dim3(HH / 128, Bsz / 128), blk, SMEM_TOT>>>(
        A2, Wh2, b2, act, HH, HH, psum, psq);
    bn_finalize<<<8, 256>>>(g2, be2);
    rowmap_stage2<<<Bsz, blk>>>(act, A2);

    // Layer 3 (K=2048 -> 32 chunks)
    gemm_mma<32, false, float><<<dim3(1024 / 128, Bsz / 128), blk, SMEM_TOT>>>(
        A2, Wh3, b3, logits, DOUT, HH, nullptr, nullptr);
    log_softmax_kernel<<<Bsz, blk>>>(logits, out);
}